// round 17
// baseline (speedup 1.0000x reference)
#include <cuda_runtime.h>
#include <math.h>

// ---------------- problem constants ----------------
#define NSPEC 400
#define NC    5530         // compact SO3 size: entries with m >= 0
#define NZO   512          // 16*32
#define SCALING 0.008164965809277261f   // 1/sqrt(15000)

// ---------------- device scratch (allocation-free) ----------------
__device__ float  g_quadw[128];
__device__ float  g_ws2[128 * NSPEC];          // [beta_in][lm]
__device__ float2 g_Fk[24 * NSPEC];            // [p][lm]
__device__ float2 g_Yc[32 * NSPEC * 16];       // [o][lm][i]  (= conj(Y)*SCALING)
__device__ float  g_dinv[40 * NC];             // [b][c] compact m>=0, includes (2l+1)
__device__ float2 g_X[16 * NSPEC * 16];        // [z][lm][i]
__device__ float2 g_Zc[(size_t)NZO * NC];      // [zo][c] compact m>=0
__device__ uchar4 g_jmapc[NC];                 // c -> (l, mi, ni)

// ---------------- helpers ----------------
// compact offset of level L: sum_{l<L} (l+1)(2l+1)
__device__ __forceinline__ int offc(int L) {
    return L == 0 ? 0 : ((L - 1) * L * (2 * L - 1)) / 3 + (3 * L * (L - 1)) / 2 + L;
}

__device__ __forceinline__ int l_of_lm(int lm) {
    int l = (int)sqrtf((float)lm);
    while ((l + 1) * (l + 1) <= lm) l++;
    while (l * l > lm) l--;
    return l;
}

// Seed d^{l0}_{m,n} at l0 = max(|m|,|n|), closed form, fp32.
__device__ float wig_seed(int l0, int m, int n, float cb, float sb) {
    int am = m < 0 ? -m : m, an = n < 0 ? -n : n;
    int k, pcb, psb, neg;
    if (an >= am) {
        k = m;
        if (n >= 0) { pcb = l0 + m; psb = l0 - m; neg = 0; }
        else        { pcb = l0 - m; psb = l0 + m; neg = (l0 + m) & 1; }
    } else {
        k = n;
        if (m >= 0) { pcb = l0 + n; psb = l0 - n; neg = (l0 + n) & 1; }
        else        { pcb = l0 - n; psb = l0 + n; neg = 0; }
    }
    int K = l0 + k;
    float C = 1.f;
    for (int i = 1; i <= K; i++) C *= (float)(2 * l0 - K + i) / (float)i;
    float v = sqrtf(C);
    for (int i = 0; i < pcb; i++) v *= cb;
    for (int i = 0; i < psb; i++) v *= sb;
    return neg ? -v : v;
}

// ---------------- const generation ----------------
__global__ void k_setup() {
    int t = threadIdx.x;
    if (t < 128) {
        float frac = (float)(2 * t + 1) / 256.f;
        float s = 0.f;
        for (int k = 0; k < 64; k++) s += sinpif((2 * k + 1) * frac) / (float)(2 * k + 1);
        g_quadw[t] = (2.f / 64.f) * sinpif(frac) * s;
    }
    for (int c = t; c < NC; c += blockDim.x) {
        int l = 0;
        while (l < 19 && offc(l + 1) <= c) l++;
        int rem = c - offc(l);
        int w = 2 * l + 1;
        int mloc = rem / w;        // m = mloc >= 0
        int ni = rem % w;
        g_jmapc[c] = make_uchar4((unsigned char)l, (unsigned char)(mloc + l),
                                 (unsigned char)ni, 0);
    }
}

// g_dinv (compact, m>=0) via fp32 recurrence: thread per (b, m, ni)
__global__ void k_dinv() {
    int id = blockIdx.x * blockDim.x + threadIdx.x;
    if (id >= 40 * 780) return;
    int q = id % 780, b = id / 780;
    int m = q / 39, n = q % 39 - 19;
    float beta = (float)M_PI * (float)(2 * b + 1) / 80.f;
    float x = cosf(beta), cb = cosf(0.5f * beta), sb = sinf(0.5f * beta);
    int an = n < 0 ? -n : n;
    int l0 = m > an ? m : an;
    float dl = wig_seed(l0, m, n, cb, sb), dlm1 = 0.f;
    float* db = g_dinv + b * NC;
    int cj = offc(l0) + m * (2 * l0 + 1) + (n + l0);
    db[cj] = (float)(2 * l0 + 1) * dl;
    float eprev = sqrtf((float)(l0 * l0 - m * m) * (float)(l0 * l0 - n * n));
    for (int l = l0 + 1; l <= 19; l++) {
        float nd;
        if (l == 1) { nd = x * dl; eprev = 1.f; }   // only m=n=0 reaches l0=0
        else {
            float el = sqrtf((float)(l * l - m * m) * (float)(l * l - n * n));
            float A = (float)(2 * l - 1) * ((float)(l * (l - 1)) * x - (float)(m * n));
            nd = __fdividef(A * dl - (float)l * eprev * dlm1, (float)(l - 1) * el);
            eprev = el;
        }
        dlm1 = dl; dl = nd;
        cj += l * (2 * l - 1) + 2 * m + 1;
        db[cj] = (float)(2 * l + 1) * dl;
    }
}

// g_ws2 via fp32 recurrence: thread per (b, mi); n = 0
__global__ void k_ws2() {
    int id = blockIdx.x * blockDim.x + threadIdx.x;
    if (id >= 128 * 39) return;
    int mi = id % 39, b = id / 39;
    int m = mi - 19;
    float beta = (float)M_PI * (float)(2 * b + 1) / 256.f;
    float x = cosf(beta), cb = cosf(0.5f * beta), sb = sinf(0.5f * beta);
    float qw = g_quadw[b];
    int l0 = m < 0 ? -m : m;
    float dl = wig_seed(l0, m, 0, cb, sb), dlm1 = 0.f;
    g_ws2[b * NSPEC + l0 * l0 + l0 + m] = qw * dl;
    float eprev = 0.f;   // sqrt((l0^2-m^2)*l0^2) = 0 since l0=|m|
    for (int l = l0 + 1; l <= 19; l++) {
        float nd;
        if (l == 1) { nd = x * dl; eprev = 1.f; }
        else {
            float el = sqrtf((float)(l * l - m * m)) * (float)l;
            float A = (float)(2 * l - 1) * (float)(l * (l - 1)) * x;
            nd = __fdividef(A * dl - (float)l * eprev * dlm1, (float)(l - 1) * el);
            eprev = el;
        }
        dlm1 = dl; dl = nd;
        g_ws2[b * NSPEC + l * l + l + m] = qw * dl;
    }
}

// g_Fk via fp32 recurrence: thread per (p, mi); n = 0, phase e^{-i m alpha}
__global__ void k_fk() {
    int id = blockIdx.x * blockDim.x + threadIdx.x;
    if (id >= 24 * 39) return;
    int mi = id % 39, p = id / 39;
    int m = mi - 19;
    float beta = ((float)M_PI / 24.f) * (float)(p / 8 + 1);
    int ai = p % 8;
    float x = cosf(beta), cb = cosf(0.5f * beta), sb = sinf(0.5f * beta);
    float sa, ca;
    sincospif(-(float)(m * ai) / 4.f, &sa, &ca);
    int l0 = m < 0 ? -m : m;
    float dl = wig_seed(l0, m, 0, cb, sb), dlm1 = 0.f;
    g_Fk[p * NSPEC + l0 * l0 + l0 + m] = make_float2(dl * ca, dl * sa);
    float eprev = 0.f;
    for (int l = l0 + 1; l <= 19; l++) {
        float nd;
        if (l == 1) { nd = x * dl; eprev = 1.f; }
        else {
            float el = sqrtf((float)(l * l - m * m)) * (float)l;
            float A = (float)(2 * l - 1) * (float)(l * (l - 1)) * x;
            nd = __fdividef(A * dl - (float)l * eprev * dlm1, (float)(l - 1) * el);
            eprev = el;
        }
        dlm1 = dl; dl = nd;
        g_Fk[p * NSPEC + l * l + l + m] = make_float2(dl * ca, dl * sa);
    }
}

// Yc[o][lm][i] = SCALING * sum_p kernel[i][o][p] * conj(F_k[p][lm])
// grid (32, 4): block = (o, 100-lm chunk); Fk chunk + kernel slice staged in smem
__global__ void __launch_bounds__(512) k_Y(const float* __restrict__ ker) {
    __shared__ float2 Fs[24 * 100];
    __shared__ float  ks[16 * 24];
    int o = blockIdx.x, lm0 = blockIdx.y * 100;
    int tid = threadIdx.x;
    for (int t = tid; t < 2400; t += 512) {
        int p = t / 100, lm = t % 100;
        Fs[t] = g_Fk[p * NSPEC + lm0 + lm];
    }
    for (int t = tid; t < 384; t += 512) {
        int i = t / 24, p = t % 24;
        ks[t] = ker[(i * 32 + o) * 24 + p] * SCALING;
    }
    __syncthreads();
    for (int c = tid; c < 1600; c += 512) {
        int lm = c >> 4, i = c & 15;
        float ar = 0.f, ai = 0.f;
        #pragma unroll
        for (int p = 0; p < 24; p++) {
            float kv = ks[i * 24 + p];
            float2 f = Fs[p * 100 + lm];
            ar += kv * f.x;
            ai += kv * f.y;
        }
        g_Yc[(size_t)o * 6400 + (lm0 + lm) * 16 + i] = make_float2(ar, -ai);
    }
}

// ---------------- alpha-DFT (m>=0 only, x real) + beta quadrature ----------------
// xs padded to 129 floats/row (bank-conflict-free 2b tiling); DFT stage tiled 2b x 2m
__global__ void __launch_bounds__(512) k_xfX(const float* __restrict__ x) {
    extern __shared__ float sm[];
    float*  xs  = sm;                               // 128 x 129 floats (padded)
    float2* dft = (float2*)(sm + 128 * 129);        // [a][m], m = 0..19
    float2* xfs = dft + 128 * 20;                   // [b][m], m = 0..19
    int zi = blockIdx.x;
    int tid = threadIdx.x;
    const float* xp = x + (size_t)zi * 16384;
    for (int t = tid; t < 16384; t += 512)
        xs[(t >> 7) * 129 + (t & 127)] = xp[t];
    for (int t = tid; t < 2560; t += 512) {
        int a = t / 20, m = t % 20;
        float s, c;
        sincospif(-(float)(m * a) / 64.0f, &s, &c);     // e^{-2pi i m a / 128}
        dft[t] = make_float2(c, s);
    }
    __syncthreads();
    // DFT tiles: 64 b-pairs x 10 m-pairs
    for (int t = tid; t < 640; t += 512) {
        int b0 = (t / 10) * 2, m0 = (t % 10) * 2;
        const float* r0 = xs + b0 * 129;
        const float* r1 = r0 + 129;
        float a00r = 0.f, a00i = 0.f, a01r = 0.f, a01i = 0.f;
        float a10r = 0.f, a10i = 0.f, a11r = 0.f, a11i = 0.f;
        #pragma unroll 8
        for (int a = 0; a < 128; a++) {
            float va = r0[a], vb = r1[a];
            float4 dd = *(const float4*)(dft + a * 20 + m0);
            a00r += va * dd.x; a00i += va * dd.y;
            a01r += va * dd.z; a01i += va * dd.w;
            a10r += vb * dd.x; a10i += vb * dd.y;
            a11r += vb * dd.z; a11i += vb * dd.w;
        }
        xfs[b0 * 20 + m0]           = make_float2(a00r, a00i);
        xfs[b0 * 20 + m0 + 1]       = make_float2(a01r, a01i);
        xfs[(b0 + 1) * 20 + m0]     = make_float2(a10r, a10i);
        xfs[(b0 + 1) * 20 + m0 + 1] = make_float2(a11r, a11i);
    }
    __syncthreads();
    int z = zi / 16, i = zi % 16;
    for (int lm = tid; lm < NSPEC; lm += 512) {
        int l = l_of_lm(lm);
        int m = lm - l * l - l;
        int ma = m < 0 ? -m : m;
        float sgn = m < 0 ? -1.f : 1.f;   // xf[b,-m] = conj(xf[b,m])
        float ar = 0.f, ai = 0.f;
        for (int b = 0; b < 128; b++) {
            float w = g_ws2[b * NSPEC + lm];
            float2 v = xfs[b * 20 + ma];
            ar += w * v.x;
            ai += w * v.y;
        }
        g_X[(z * NSPEC + lm) * 16 + i] = make_float2(ar, sgn * ai);
    }
}

// ---------------- Zc[zo][c] = sum_i X[z,i,lm_m] * Yc[o,lm_n,i], m>=0 only -------
__global__ void __launch_bounds__(512) k_Z() {
    extern __shared__ float2 sm2[];
    float2* Xs = sm2;          // [i][400]
    float2* Ys = sm2 + 6400;   // [i][400]
    int zo = blockIdx.x;
    int z = zo >> 5, o = zo & 31;
    int tid = threadIdx.x;
    for (int t = tid; t < 6400; t += blockDim.x) {
        int lm = t >> 4, i = t & 15;
        Xs[i * NSPEC + lm] = g_X[z * 6400 + t];
        Ys[i * NSPEC + lm] = g_Yc[o * 6400 + t];
    }
    __syncthreads();
    for (int c = tid; c < NC; c += blockDim.x) {
        uchar4 mp = g_jmapc[c];
        int l = mp.x;
        int lmm = l * l + mp.y, lmn = l * l + mp.z;
        float zr = 0.f, zi = 0.f;
        #pragma unroll
        for (int i = 0; i < 16; i++) {
            float2 xv = Xs[i * NSPEC + lmm];
            float2 yv = Ys[i * NSPEC + lmn];
            zr += xv.x * yv.x - xv.y * yv.y;
            zi += xv.x * yv.y + xv.y * yv.x;
        }
        g_Zc[(size_t)zo * NC + c] = make_float2(zr, zi);
    }
}

// ---------------- synthesis: Hermitian, compact Z, register-tiled stages --------
// grid (512, 5), block 512; each block: one zo, 8 output betas = 2 passes x 4.
__global__ void __launch_bounds__(512, 2) k_syn(const float* __restrict__ bias,
                                                float* __restrict__ out) {
    extern __shared__ float smraw[];
    float2* Zs = (float2*)smraw;         // 5530 compact (m>=0)
    float2* Ws = Zs + NC;                // 4 x 780   [sub][m][ni]
    float2* Ts = Ws + 3120;              // 4 x 800   [sub][m][g]
    float2* e2 = Ts + 3200;              // 39*20     [k][g]: e^{i (k-19) g pi/20}
    int zo = blockIdx.x;
    int tid = threadIdx.x;
    const int nth = 512;

    for (int t = tid; t < NC; t += nth) Zs[t] = g_Zc[(size_t)zo * NC + t];
    for (int t = tid; t < 780; t += nth) {
        int k = t / 20, g = t % 20;
        float s, c;
        sincospif((float)((k - 19) * g) / 20.0f, &s, &c);
        e2[t] = make_float2(c, s);
    }
    __syncthreads();

    float bias_o = bias[zo & 31];
    float* outbase = out + (size_t)zo * 64000;

    for (int bg = 0; bg < 2; bg++) {
        int b0 = blockIdx.y * 8 + bg * 4;
        const float* d0 = g_dinv + b0 * NC;
        const float* d1 = d0 + NC;
        const float* d2 = d1 + NC;
        const float* d3 = d2 + NC;

        // stage 1: W[sub][m][ni] for 4 betas from one Z scan
        for (int q = tid; q < 780; q += nth) {
            int m = q / 39, n = q % 39 - 19;
            int an = n < 0 ? -n : n;
            int lmin = m > an ? m : an;
            int cj = offc(lmin) + m * (2 * lmin + 1) + (n + lmin);
            float w0r = 0.f, w0i = 0.f, w1r = 0.f, w1i = 0.f;
            float w2r = 0.f, w2i = 0.f, w3r = 0.f, w3i = 0.f;
            for (int l = lmin; l < 20; l++) {
                float2 zv = Zs[cj];
                float da = d0[cj], db = d1[cj], dc = d2[cj], dd = d3[cj];
                w0r += zv.x * da; w0i += zv.y * da;
                w1r += zv.x * db; w1i += zv.y * db;
                w2r += zv.x * dc; w2i += zv.y * dc;
                w3r += zv.x * dd; w3i += zv.y * dd;
                cj += (l + 1) * (2 * l + 1) + 2 * m + 1;
            }
            Ws[q]        = make_float2(w0r, w0i);
            Ws[780 + q]  = make_float2(w1r, w1i);
            Ws[1560 + q] = make_float2(w2r, w2i);
            Ws[2340 + q] = make_float2(w3r, w3i);
        }
        __syncthreads();

        // stage 2: 2m x 2g tiles over adjacent g (g0, g0+1); A = even-ni, B = odd-ni
        // T[g] = A + B; T[g+20] = B - A  (n = ni-19 parity; g covers 0..19 here,
        // +20 columns come from the parity twist). 4 subs x 100 tiles.
        for (int t = tid; t < 400; t += nth) {
            int sub = t / 100;
            int r = t - sub * 100;
            int m0 = (r / 10) * 2, g0 = (r % 10) * 2;
            const float2* w0 = Ws + sub * 780 + m0 * 39;
            const float2* w1 = w0 + 39;
            float A00r=0,A00i=0,A01r=0,A01i=0,A10r=0,A10i=0,A11r=0,A11i=0;
            float B00r=0,B00i=0,B01r=0,B01i=0,B10r=0,B10i=0,B11r=0,B11i=0;
            #pragma unroll
            for (int ni = 0; ni < 38; ni += 2) {
                float2 wa = w0[ni], wb = w1[ni];
                float2 qa = e2[ni * 20 + g0], qb = e2[ni * 20 + g0 + 1];
                A00r += wa.x*qa.x - wa.y*qa.y; A00i += wa.x*qa.y + wa.y*qa.x;
                A01r += wa.x*qb.x - wa.y*qb.y; A01i += wa.x*qb.y + wa.y*qb.x;
                A10r += wb.x*qa.x - wb.y*qa.y; A10i += wb.x*qa.y + wb.y*qa.x;
                A11r += wb.x*qb.x - wb.y*qb.y; A11i += wb.x*qb.y + wb.y*qb.x;
                wa = w0[ni + 1]; wb = w1[ni + 1];
                qa = e2[(ni + 1) * 20 + g0]; qb = e2[(ni + 1) * 20 + g0 + 1];
                B00r += wa.x*qa.x - wa.y*qa.y; B00i += wa.x*qa.y + wa.y*qa.x;
                B01r += wa.x*qb.x - wa.y*qb.y; B01i += wa.x*qb.y + wa.y*qb.x;
                B10r += wb.x*qa.x - wb.y*qa.y; B10i += wb.x*qa.y + wb.y*qa.x;
                B11r += wb.x*qb.x - wb.y*qb.y; B11i += wb.x*qb.y + wb.y*qb.x;
            }
            {   // ni = 38 (even)
                float2 wa = w0[38], wb = w1[38];
                float2 qa = e2[38 * 20 + g0], qb = e2[38 * 20 + g0 + 1];
                A00r += wa.x*qa.x - wa.y*qa.y; A00i += wa.x*qa.y + wa.y*qa.x;
                A01r += wa.x*qb.x - wa.y*qb.y; A01i += wa.x*qb.y + wa.y*qb.x;
                A10r += wb.x*qa.x - wb.y*qa.y; A10i += wb.x*qa.y + wb.y*qa.x;
                A11r += wb.x*qb.x - wb.y*qb.y; A11i += wb.x*qb.y + wb.y*qb.x;
            }
            float2* Tp = Ts + sub * 800;
            Tp[m0*40 + g0]          = make_float2(A00r + B00r, A00i + B00i);
            Tp[m0*40 + g0 + 20]     = make_float2(B00r - A00r, B00i - A00i);
            Tp[m0*40 + g0 + 1]      = make_float2(A01r + B01r, A01i + B01i);
            Tp[m0*40 + g0 + 21]     = make_float2(B01r - A01r, B01i - A01i);
            Tp[(m0+1)*40 + g0]      = make_float2(A10r + B10r, A10i + B10i);
            Tp[(m0+1)*40 + g0 + 20] = make_float2(B10r - A10r, B10i - A10i);
            Tp[(m0+1)*40 + g0 + 1]  = make_float2(A11r + B11r, A11i + B11i);
            Tp[(m0+1)*40 + g0 + 21] = make_float2(B11r - A11r, B11i - A11i);
        }
        __syncthreads();

        // stage 3: 2a x 2g tiles; E = even-m, O = odd-m real partials.
        // g covers ALL 20 pairs (a-parity twist gives rows a+20): 4 subs x 200.
        // out[a][g] = T0 + 2(E+O); out[a+20][g] = T0 + 2(E-O)
        for (int t = tid; t < 800; t += nth) {
            int sub = t / 200;
            int r = t - sub * 200;
            int a0 = (r / 20) * 2, gp = r % 20;
            int g0 = 2 * gp;
            const float2* Tp = Ts + sub * 800;
            float E00=0,O00=0,E01=0,O01=0,E10=0,O10=0,E11=0,O11=0;
            #pragma unroll
            for (int m = 1; m < 19; m += 2) {
                float2 t0 = Tp[m*40 + g0], t1 = Tp[m*40 + g0 + 1];
                float2 ea = e2[(m+19)*20 + a0], eb = e2[(m+19)*20 + a0 + 1];
                O00 += t0.x*ea.x - t0.y*ea.y; O01 += t1.x*ea.x - t1.y*ea.y;
                O10 += t0.x*eb.x - t0.y*eb.y; O11 += t1.x*eb.x - t1.y*eb.y;
                t0 = Tp[(m+1)*40 + g0]; t1 = Tp[(m+1)*40 + g0 + 1];
                ea = e2[(m+20)*20 + a0]; eb = e2[(m+20)*20 + a0 + 1];
                E00 += t0.x*ea.x - t0.y*ea.y; E01 += t1.x*ea.x - t1.y*ea.y;
                E10 += t0.x*eb.x - t0.y*eb.y; E11 += t1.x*eb.x - t1.y*eb.y;
            }
            {   // m = 19 (odd)
                float2 t0 = Tp[19*40 + g0], t1 = Tp[19*40 + g0 + 1];
                float2 ea = e2[38*20 + a0], eb = e2[38*20 + a0 + 1];
                O00 += t0.x*ea.x - t0.y*ea.y; O01 += t1.x*ea.x - t1.y*ea.y;
                O10 += t0.x*eb.x - t0.y*eb.y; O11 += t1.x*eb.x - t1.y*eb.y;
            }
            float T0g0 = Tp[g0].x, T0g1 = Tp[g0 + 1].x;
            float* rb = outbase + (size_t)(b0 + sub) * 1600;
            rb[a0*40 + g0]          = T0g0 + 2.f*(E00 + O00) + bias_o;
            rb[a0*40 + g0 + 1]      = T0g1 + 2.f*(E01 + O01) + bias_o;
            rb[(a0+20)*40 + g0]     = T0g0 + 2.f*(E00 - O00) + bias_o;
            rb[(a0+20)*40 + g0 + 1] = T0g1 + 2.f*(E01 - O01) + bias_o;
            rb[(a0+1)*40 + g0]      = T0g0 + 2.f*(E10 + O10) + bias_o;
            rb[(a0+1)*40 + g0 + 1]  = T0g1 + 2.f*(E11 + O11) + bias_o;
            rb[(a0+21)*40 + g0]     = T0g0 + 2.f*(E10 - O10) + bias_o;
            rb[(a0+21)*40 + g0 + 1] = T0g1 + 2.f*(E11 - O11) + bias_o;
        }
        __syncthreads();
    }
}

// ---------------- launch ----------------
extern "C" void kernel_launch(void* const* d_in, const int* in_sizes, int n_in,
                              void* d_out, int out_size) {
    const float* x    = (const float*)d_in[0];
    const float* ker  = (const float*)d_in[1];
    const float* bias = (const float*)d_in[2];
    float* out = (float*)d_out;

    const int SM_XFX = 128 * 129 * 4 + 2 * (128 * 20) * 8;              // 107008
    const int SM_Z   = 2 * 6400 * 8;                                    // 102400
    const int SM_SYN = (NC + 3120 + 3200 + 780) * 8;                    // 101040

    cudaFuncSetAttribute(k_xfX, cudaFuncAttributeMaxDynamicSharedMemorySize, SM_XFX);
    cudaFuncSetAttribute(k_Z,   cudaFuncAttributeMaxDynamicSharedMemorySize, SM_Z);
    cudaFuncSetAttribute(k_syn, cudaFuncAttributeMaxDynamicSharedMemorySize, SM_SYN);

    k_setup<<<1, 256>>>();
    k_ws2<<<(128 * 39 + 255) / 256, 256>>>();
    k_fk<<<(24 * 39 + 255) / 256, 256>>>();
    k_dinv<<<(40 * 780 + 255) / 256, 256>>>();
    k_Y<<<dim3(32, 4), 512>>>(ker);
    k_xfX<<<256, 512, SM_XFX>>>(x);
    k_Z<<<512, 512, SM_Z>>>();
    k_syn<<<dim3(NZO, 5), 512, SM_SYN>>>(bias, out);
}